// round 13
// baseline (speedup 1.0000x reference)
#include <cuda_runtime.h>
#include <cuda_fp16.h>
#include <stdint.h>

// Problem constants
#define TT   256
#define BB   128
#define NIN  784
#define NHID 512
#define NOUT 128
#define MM   (TT*BB)        // 32768 (t,b) pairs
#define KPAD 832            // 784 padded to 13*64
#define NCH  13             // gemm1 K chunks of 64
#define NCH2B 16            // gemm2 K chunks of 32 (512/32)
#define MTILES (MM/128)     // 256

// CUBA constants (exactly fp32-rounded like JAX)
#define C_A ((float)(1e-6*(1.0/6e-6)))           // 0.16666667f
#define C_D ((float)(1.0 - 1e-6*(1.0/6e-6)))     // 0.8333333f

// ---- scratch (device globals; no allocations allowed) ----
__device__ __half   g_a16 [(size_t)MM*KPAD];   // spikes fp16 K-padded    54.5 MB
__device__ __half   g_bhi [NHID*KPAD];         // w_hidden hi fp16        0.85 MB
__device__ __half   g_blo [NHID*KPAD];         // w_hidden lo fp16        0.85 MB
__device__ __half   g_ohi [NOUT*NHID];         // w_out hi fp16           128 KB
__device__ __half   g_olo [NOUT*NHID];         // w_out lo fp16           128 KB
__device__ float    g_ch  [(size_t)MM*NHID];   // hidden synaptic input   67 MB
__device__ __half   g_sh  [(size_t)MM*NHID];   // hidden spikes fp16      33.5 MB
__device__ float    g_co  [MM*NOUT];           // output synaptic input   16.8 MB

// ================= PTX helpers =================
__device__ __forceinline__ uint32_t smem_u32(const void* p) {
    uint32_t a;
    asm("{ .reg .u64 t; cvta.to.shared.u64 t, %1; cvt.u32.u64 %0, t; }" : "=r"(a) : "l"(p));
    return a;
}
#define CP_ASYNC16(dst, src) \
    asm volatile("cp.async.cg.shared.global [%0], [%1], 16;" :: "r"(dst), "l"(src))
#define CP_COMMIT()  asm volatile("cp.async.commit_group;" ::: "memory")
#define CP_WAIT(n)   asm volatile("cp.async.wait_group %0;" :: "n"(n) : "memory")

#define LDSM_X4(r0,r1,r2,r3, a) \
    asm volatile("ldmatrix.sync.aligned.m8n8.x4.shared.b16 {%0,%1,%2,%3}, [%4];" \
        : "=r"(r0),"=r"(r1),"=r"(r2),"=r"(r3) : "r"(a))
#define MMA16816(d, a0,a1,a2,a3, b0,b1) \
    asm volatile("mma.sync.aligned.m16n8k16.row.col.f32.f16.f16.f32 " \
        "{%0,%1,%2,%3}, {%4,%5,%6,%7}, {%8,%9}, {%0,%1,%2,%3};" \
        : "+f"((d)[0]),"+f"((d)[1]),"+f"((d)[2]),"+f"((d)[3]) \
        : "r"(a0),"r"(a1),"r"(a2),"r"(a3),"r"(b0),"r"(b1))

#define SWZ(off)   ((off) ^ (((off) >> 3) & 0x70))
#define SWZ64(off) ((off) ^ (((off) >> 3) & 0x30))

// ================= prep kernel: A conversion + weight splits, fused =================
#define AGRP 104
#define A16_BLOCKS ((MM*AGRP + 255)/256)
#define WS_ELEMS   (NHID*KPAD + NOUT*NHID)
#define WS_BLOCKS  ((WS_ELEMS + 255)/256)

__global__ void k_prep(const float* __restrict__ spikes,
                       const float* __restrict__ wh,
                       const float* __restrict__ wo) {
    if (blockIdx.x < A16_BLOCKS) {
        int idx = blockIdx.x*blockDim.x + threadIdx.x;
        if (idx >= MM*AGRP) return;
        int m = idx / AGRP, grp = idx - m*AGRP;
        uint4 out;
        if (grp < 98) {
            const float4* src = (const float4*)(spikes + (size_t)m*NIN + grp*8);
            float4 v0 = __ldcs(src);
            float4 v1 = __ldcs(src + 1);
            __half2 h0 = __floats2half2_rn(v0.x, v0.y);
            __half2 h1 = __floats2half2_rn(v0.z, v0.w);
            __half2 h2 = __floats2half2_rn(v1.x, v1.y);
            __half2 h3 = __floats2half2_rn(v1.z, v1.w);
            out.x = *(uint32_t*)&h0; out.y = *(uint32_t*)&h1;
            out.z = *(uint32_t*)&h2; out.w = *(uint32_t*)&h3;
        } else {
            out.x = out.y = out.z = out.w = 0u;
        }
        // plain store: g_a16 is re-read 4x by gemm1 -> keep L2-resident
        *(uint4*)(g_a16 + (size_t)m*KPAD + grp*8) = out;
    } else {
        int idx = (blockIdx.x - A16_BLOCKS)*blockDim.x + threadIdx.x;
        if (idx < NHID*KPAD) {
            int h = idx / KPAD, k = idx - h*KPAD;
            __half hi = __float2half_rn(0.f), lo = __float2half_rn(0.f);
            if (k < NIN) {
                float wv = wh[h*NIN + k];
                hi = __float2half_rn(wv);
                lo = __float2half_rn(wv - __half2float(hi));
            }
            g_bhi[idx] = hi;
            g_blo[idx] = lo;
        } else {
            int j = idx - NHID*KPAD;
            if (j < NOUT*NHID) {
                float wv = wo[j];
                __half hi = __float2half_rn(wv);
                g_ohi[j] = hi;
                g_olo[j] = __float2half_rn(wv - __half2float(hi));
            }
        }
    }
}

// ================= GEMM1 (frozen R6 core): warp tile 32x64, warps 4(m) x 2(n) =================
#define STAGE_BYTES 49152

__global__ void __launch_bounds__(256, 2) k_gemm1tc() {
    extern __shared__ char smem[];
    const int tid    = threadIdx.x;
    const int wid    = tid >> 5;
    const int lane   = tid & 31;
    const int warp_m = wid >> 1;
    const int warp_n = wid &  1;
    const int m_base = blockIdx.x * 128;
    const int n_base = blockIdx.y * 128;

    const uint32_t sbase = smem_u32(smem);

    auto load_tile = [&](int kc, int s) {
        const uint32_t st = sbase + s * STAGE_BYTES;
        const int kcol = kc * 64;
        #pragma unroll
        for (int it = 0; it < 4; it++) {
            int g = it * 256 + tid;
            int row = g >> 3, sub = g & 7;
            uint32_t off = row * 128 + sub * 16;
            const char* src = (const char*)(g_a16 + (size_t)(m_base + row)*KPAD + kcol) + sub*16;
            CP_ASYNC16(st + SWZ(off), src);
        }
        #pragma unroll
        for (int it = 0; it < 4; it++) {
            int g = it * 256 + tid;
            int row = g >> 3, sub = g & 7;
            uint32_t off = row * 128 + sub * 16;
            const char* srch = (const char*)(g_bhi + (size_t)(n_base + row)*KPAD + kcol) + sub*16;
            const char* srcl = (const char*)(g_blo + (size_t)(n_base + row)*KPAD + kcol) + sub*16;
            CP_ASYNC16(st + 16384 + SWZ(off), srch);
            CP_ASYNC16(st + 32768 + SWZ(off), srcl);
        }
        CP_COMMIT();
    };

    float acc[2][8][4];
    #pragma unroll
    for (int i = 0; i < 2; i++)
        #pragma unroll
        for (int j = 0; j < 8; j++)
            #pragma unroll
            for (int q = 0; q < 4; q++) acc[i][j][q] = 0.f;

    load_tile(0, 0);

    const int lrow = lane & 15, lcol = (lane >> 4) * 16;

    #pragma unroll 1
    for (int c = 0; c < NCH; c++) {
        const int buf = c & 1;
        if (c + 1 < NCH) { load_tile(c + 1, buf ^ 1); CP_WAIT(1); }
        else            { CP_WAIT(0); }
        __syncthreads();

        const uint32_t sA = sbase + buf * STAGE_BYTES;
        const uint32_t sBh = sA + 16384;
        const uint32_t sBl = sA + 32768;

        #pragma unroll
        for (int ks = 0; ks < 4; ks++) {
            uint32_t a[2][4], bh[4][4], bl[4][4];
            #pragma unroll
            for (int mt = 0; mt < 2; mt++) {
                uint32_t off = (uint32_t)(warp_m*32 + mt*16 + lrow)*128 + ks*32 + lcol;
                LDSM_X4(a[mt][0], a[mt][1], a[mt][2], a[mt][3], sA + SWZ(off));
            }
            #pragma unroll
            for (int nt = 0; nt < 4; nt++) {
                uint32_t off = (uint32_t)(warp_n*64 + nt*16 + lrow)*128 + ks*32 + lcol;
                uint32_t so = SWZ(off);
                LDSM_X4(bh[nt][0], bh[nt][1], bh[nt][2], bh[nt][3], sBh + so);
                LDSM_X4(bl[nt][0], bl[nt][1], bl[nt][2], bl[nt][3], sBl + so);
            }
            #pragma unroll
            for (int mt = 0; mt < 2; mt++)
                #pragma unroll
                for (int nt = 0; nt < 4; nt++) {
                    MMA16816(acc[mt][nt*2+0], a[mt][0],a[mt][1],a[mt][2],a[mt][3],
                             bh[nt][0], bh[nt][2]);
                    MMA16816(acc[mt][nt*2+1], a[mt][0],a[mt][1],a[mt][2],a[mt][3],
                             bh[nt][1], bh[nt][3]);
                    MMA16816(acc[mt][nt*2+0], a[mt][0],a[mt][1],a[mt][2],a[mt][3],
                             bl[nt][0], bl[nt][2]);
                    MMA16816(acc[mt][nt*2+1], a[mt][0],a[mt][1],a[mt][2],a[mt][3],
                             bl[nt][1], bl[nt][3]);
                }
        }
        __syncthreads();
    }

    const int erow = lane >> 2, ecol = (lane & 3) * 2;
    #pragma unroll
    for (int mt = 0; mt < 2; mt++) {
        #pragma unroll
        for (int nt = 0; nt < 8; nt++) {
            int col = n_base + warp_n*64 + nt*8 + ecol;
            int r0  = m_base + warp_m*32 + mt*16 + erow;
            float2 v0; v0.x = acc[mt][nt][0]; v0.y = acc[mt][nt][1];
            float2 v1; v1.x = acc[mt][nt][2]; v1.y = acc[mt][nt][3];
            *(float2*)(g_ch + (size_t)r0*NHID + col)       = v0;
            *(float2*)(g_ch + (size_t)(r0 + 8)*NHID + col) = v1;
        }
    }
}

// ================= GEMM2: depth-4 pipeline, 32-col chunks, SW64 swizzle =================
// Stage = A 8KB + Bhi 8KB + Blo 8KB = 24KB; 4 stages = 96KB (2 CTAs/SM kept).
// Per-accumulator K-order identical to the depth-2/64-col version -> bit-identical.
#define S2_BYTES 24576

__global__ void __launch_bounds__(256, 2) k_gemm2tc() {
    extern __shared__ char smem[];
    const int tid    = threadIdx.x;
    const int wid    = tid >> 5;
    const int lane   = tid & 31;
    const int warp_m = wid >> 1;
    const int warp_n = wid &  1;
    const int m_base = blockIdx.x * 128;

    const uint32_t sbase = smem_u32(smem);

    // chunk kc covers K columns [kc*32, kc*32+32) = 64 bytes per row
    auto load_chunk = [&](int kc, int s) {
        const uint32_t st = sbase + s * S2_BYTES;
        const int kb = kc * 64;                   // byte offset within row
        // A: 128 rows x 4 granules = 512; Bh: 512; Bl: 512 -> 6 per thread
        #pragma unroll
        for (int it = 0; it < 2; it++) {
            int g = it * 256 + tid;
            int row = g >> 2, sub = g & 3;
            uint32_t off = row * 64 + sub * 16;
            const char* src = (const char*)g_sh + ((size_t)(m_base + row)*NHID)*2 + kb + sub*16;
            CP_ASYNC16(st + SWZ64(off), src);
        }
        #pragma unroll
        for (int it = 0; it < 2; it++) {
            int g = it * 256 + tid;
            int row = g >> 2, sub = g & 3;
            uint32_t off = row * 64 + sub * 16;
            const char* srch = (const char*)g_ohi + ((size_t)row*NHID)*2 + kb + sub*16;
            const char* srcl = (const char*)g_olo + ((size_t)row*NHID)*2 + kb + sub*16;
            CP_ASYNC16(st + 8192  + SWZ64(off), srch);
            CP_ASYNC16(st + 16384 + SWZ64(off), srcl);
        }
        CP_COMMIT();
    };

    float acc[2][8][4];
    #pragma unroll
    for (int i = 0; i < 2; i++)
        #pragma unroll
        for (int j = 0; j < 8; j++)
            #pragma unroll
            for (int q = 0; q < 4; q++) acc[i][j][q] = 0.f;

    load_chunk(0, 0);
    load_chunk(1, 1);
    load_chunk(2, 2);

    const int lrow = lane & 15, lcol = (lane >> 4) * 16;

    #pragma unroll 1
    for (int c = 0; c < NCH2B; c++) {
        if      (c < NCH2B - 2) CP_WAIT(2);
        else if (c == NCH2B - 2) CP_WAIT(1);
        else                     CP_WAIT(0);
        __syncthreads();
        if (c + 3 < NCH2B) load_chunk(c + 3, (c + 3) & 3);

        const uint32_t sA  = sbase + (c & 3) * S2_BYTES;
        const uint32_t sBh = sA + 8192;
        const uint32_t sBl = sA + 16384;

        #pragma unroll
        for (int ks = 0; ks < 2; ks++) {
            uint32_t a[2][4], bh[4][4], bl[4][4];
            #pragma unroll
            for (int mt = 0; mt < 2; mt++) {
                uint32_t off = (uint32_t)(warp_m*32 + mt*16 + lrow)*64 + ks*32 + lcol;
                LDSM_X4(a[mt][0], a[mt][1], a[mt][2], a[mt][3], sA + SWZ64(off));
            }
            #pragma unroll
            for (int nt = 0; nt < 4; nt++) {
                uint32_t off = (uint32_t)(warp_n*64 + nt*16 + lrow)*64 + ks*32 + lcol;
                uint32_t so = SWZ64(off);
                LDSM_X4(bh[nt][0], bh[nt][1], bh[nt][2], bh[nt][3], sBh + so);
                LDSM_X4(bl[nt][0], bl[nt][1], bl[nt][2], bl[nt][3], sBl + so);
            }
            #pragma unroll
            for (int mt = 0; mt < 2; mt++)
                #pragma unroll
                for (int nt = 0; nt < 4; nt++) {
                    MMA16816(acc[mt][nt*2+0], a[mt][0],a[mt][1],a[mt][2],a[mt][3],
                             bh[nt][0], bh[nt][2]);
                    MMA16816(acc[mt][nt*2+1], a[mt][0],a[mt][1],a[mt][2],a[mt][3],
                             bh[nt][1], bh[nt][3]);
                    MMA16816(acc[mt][nt*2+0], a[mt][0],a[mt][1],a[mt][2],a[mt][3],
                             bl[nt][0], bl[nt][2]);
                    MMA16816(acc[mt][nt*2+1], a[mt][0],a[mt][1],a[mt][2],a[mt][3],
                             bl[nt][1], bl[nt][3]);
                }
        }
    }

    const int erow = lane >> 2, ecol = (lane & 3) * 2;
    #pragma unroll
    for (int mt = 0; mt < 2; mt++) {
        #pragma unroll
        for (int nt = 0; nt < 8; nt++) {
            int col = warp_n*64 + nt*8 + ecol;
            int r0  = m_base + warp_m*32 + mt*16 + erow;
            float2 v0; v0.x = acc[mt][nt][0]; v0.y = acc[mt][nt][1];
            float2 v1; v1.x = acc[mt][nt][2]; v1.y = acc[mt][nt][3];
            *(float2*)(g_co + (size_t)r0*NOUT + col)       = v0;
            *(float2*)(g_co + (size_t)(r0 + 8)*NOUT + col) = v1;
        }
    }
}

// ================= LIF scan: float2-wide, prefetch 16 =================
__global__ void k_lif() {
    int g2 = blockIdx.x*blockDim.x + threadIdx.x;   // pair index: 0 .. BB*NHID/2-1
    const float2* src = ((const float2*)g_ch) + g2;
    __half2*      dst = ((__half2*)g_sh) + g2;
    const int STRIDE2 = BB*NHID/2;                  // 32768 float2 per timestep
    float vx = 0.f, vy = 0.f, cx = 0.f, cy = 0.f;
    float2 xs[16];
    #pragma unroll
    for (int p = 0; p < 16; p++) xs[p] = __ldcs(src + (size_t)p*STRIDE2);
    #pragma unroll 1
    for (int t0 = 0; t0 < TT; t0 += 16) {
        #pragma unroll
        for (int p = 0; p < 16; p++) {
            float2 x = xs[p];
            int tn = t0 + 16 + p;
            if (tn < TT) xs[p] = __ldcs(src + (size_t)tn*STRIDE2);
            vx = vx + C_A*(cx - vx);
            vy = vy + C_A*(cy - vy);
            cx = cx*C_D + x.x;
            cy = cy*C_D + x.y;
            bool zx = vx > 1.0f, zy = vy > 1.0f;
            if (zx) vx = 0.f;
            if (zy) vy = 0.f;
            dst[(size_t)(t0 + p)*STRIDE2] = __floats2half2_rn(zx ? 1.f : 0.f,
                                                              zy ? 1.f : 0.f);
        }
    }
}

// ================= LI scan (prefetch 32) =================
__global__ void k_li(float* __restrict__ out) {
    int gid = blockIdx.x*blockDim.x + threadIdx.x;   // b*128 + o
    float v = 0.0f, cur = 0.0f;
    float xs[32];
    #pragma unroll
    for (int p = 0; p < 32; p++) xs[p] = __ldcs(g_co + p*(BB*NOUT) + gid);
    #pragma unroll 1
    for (int t0 = 0; t0 < TT; t0 += 32) {
        #pragma unroll
        for (int p = 0; p < 32; p++) {
            float x = xs[p];
            int tn = t0 + 32 + p;
            if (tn < TT) xs[p] = __ldcs(g_co + tn*(BB*NOUT) + gid);
            v   = v + C_A*(cur - v);
            cur = cur*C_D + x;
            __stcs(out + (t0 + p)*(BB*NOUT) + gid, v);
        }
    }
}

// ================= launch =================
extern "C" void kernel_launch(void* const* d_in, const int* in_sizes, int n_in,
                              void* d_out, int out_size) {
    const float *spikes = nullptr, *wh = nullptr, *wo = nullptr;
    for (int i = 0; i < n_in; i++) {
        if      (in_sizes[i] == TT*BB*NIN) spikes = (const float*)d_in[i];
        else if (in_sizes[i] == NHID*NIN)  wh     = (const float*)d_in[i];
        else if (in_sizes[i] == NOUT*NHID) wo     = (const float*)d_in[i];
    }
    cudaFuncSetAttribute(k_gemm1tc, cudaFuncAttributeMaxDynamicSharedMemorySize,
                         2*STAGE_BYTES);
    cudaFuncSetAttribute(k_gemm2tc, cudaFuncAttributeMaxDynamicSharedMemorySize,
                         4*S2_BYTES);
    k_prep   <<<A16_BLOCKS + WS_BLOCKS, 256>>>(spikes, wh, wo);
    k_gemm1tc<<<dim3(MTILES, NHID/128), 256, 2*STAGE_BYTES>>>();
    k_lif    <<<(BB*NHID/2)/128, 128>>>();
    k_gemm2tc<<<MTILES, 256, 4*S2_BYTES>>>();
    k_li     <<<(BB*NOUT)/64, 64>>>((float*)d_out);
}

// round 14
// speedup vs baseline: 1.0228x; 1.0228x over previous
#include <cuda_runtime.h>
#include <cuda_fp16.h>
#include <stdint.h>

// Problem constants
#define TT   256
#define BB   128
#define NIN  784
#define NHID 512
#define NOUT 128
#define MM   (TT*BB)        // 32768 (t,b) pairs
#define KPAD 832            // 784 padded to 13*64
#define NCH  13             // gemm1 K chunks of 64
#define NCH2 8              // gemm2 K chunks of 64 (512/64)
#define MTILES (MM/128)     // 256

// CUBA constants (exactly fp32-rounded like JAX)
#define C_A ((float)(1e-6*(1.0/6e-6)))           // 0.16666667f
#define C_D ((float)(1.0 - 1e-6*(1.0/6e-6)))     // 0.8333333f

// ---- scratch (device globals; no allocations allowed) ----
__device__ __half   g_a16 [(size_t)MM*KPAD];   // spikes fp16 K-padded    54.5 MB
__device__ __half   g_bhi [NHID*KPAD];         // w_hidden hi fp16        0.85 MB
__device__ __half   g_blo [NHID*KPAD];         // w_hidden lo fp16        0.85 MB
__device__ __half   g_ohi [NOUT*NHID];         // w_out hi fp16           128 KB
__device__ __half   g_olo [NOUT*NHID];         // w_out lo fp16           128 KB
__device__ float    g_ch  [(size_t)MM*NHID];   // hidden synaptic input   67 MB
__device__ __half   g_sh  [(size_t)MM*NHID];   // hidden spikes fp16      33.5 MB
__device__ float    g_co  [MM*NOUT];           // output synaptic input   16.8 MB

// ================= PTX helpers =================
__device__ __forceinline__ uint32_t smem_u32(const void* p) {
    uint32_t a;
    asm("{ .reg .u64 t; cvta.to.shared.u64 t, %1; cvt.u32.u64 %0, t; }" : "=r"(a) : "l"(p));
    return a;
}
#define CP_ASYNC16(dst, src) \
    asm volatile("cp.async.cg.shared.global [%0], [%1], 16;" :: "r"(dst), "l"(src))
#define CP_COMMIT()  asm volatile("cp.async.commit_group;" ::: "memory")
#define CP_WAIT(n)   asm volatile("cp.async.wait_group %0;" :: "n"(n) : "memory")

#define LDSM_X4(r0,r1,r2,r3, a) \
    asm volatile("ldmatrix.sync.aligned.m8n8.x4.shared.b16 {%0,%1,%2,%3}, [%4];" \
        : "=r"(r0),"=r"(r1),"=r"(r2),"=r"(r3) : "r"(a))
#define MMA16816(d, a0,a1,a2,a3, b0,b1) \
    asm volatile("mma.sync.aligned.m16n8k16.row.col.f32.f16.f16.f32 " \
        "{%0,%1,%2,%3}, {%4,%5,%6,%7}, {%8,%9}, {%0,%1,%2,%3};" \
        : "+f"((d)[0]),"+f"((d)[1]),"+f"((d)[2]),"+f"((d)[3]) \
        : "r"(a0),"r"(a1),"r"(a2),"r"(a3),"r"(b0),"r"(b1))

#define SWZ(off) ((off) ^ (((off) >> 3) & 0x70))

// ================= prep kernel: A conversion + weight splits, fused =================
#define AGRP 104
#define A16_BLOCKS ((MM*AGRP + 255)/256)
#define WS_ELEMS   (NHID*KPAD + NOUT*NHID)
#define WS_BLOCKS  ((WS_ELEMS + 255)/256)

__global__ void k_prep(const float* __restrict__ spikes,
                       const float* __restrict__ wh,
                       const float* __restrict__ wo) {
    if (blockIdx.x < A16_BLOCKS) {
        int idx = blockIdx.x*blockDim.x + threadIdx.x;
        if (idx >= MM*AGRP) return;
        int m = idx / AGRP, grp = idx - m*AGRP;
        uint4 out;
        if (grp < 98) {
            const float4* src = (const float4*)(spikes + (size_t)m*NIN + grp*8);
            float4 v0 = __ldcs(src);
            float4 v1 = __ldcs(src + 1);
            __half2 h0 = __floats2half2_rn(v0.x, v0.y);
            __half2 h1 = __floats2half2_rn(v0.z, v0.w);
            __half2 h2 = __floats2half2_rn(v1.x, v1.y);
            __half2 h3 = __floats2half2_rn(v1.z, v1.w);
            out.x = *(uint32_t*)&h0; out.y = *(uint32_t*)&h1;
            out.z = *(uint32_t*)&h2; out.w = *(uint32_t*)&h3;
        } else {
            out.x = out.y = out.z = out.w = 0u;
        }
        // plain store: g_a16 is re-read 4x by gemm1 -> keep L2-resident
        *(uint4*)(g_a16 + (size_t)m*KPAD + grp*8) = out;
    } else {
        int idx = (blockIdx.x - A16_BLOCKS)*blockDim.x + threadIdx.x;
        if (idx < NHID*KPAD) {
            int h = idx / KPAD, k = idx - h*KPAD;
            __half hi = __float2half_rn(0.f), lo = __float2half_rn(0.f);
            if (k < NIN) {
                float wv = wh[h*NIN + k];
                hi = __float2half_rn(wv);
                lo = __float2half_rn(wv - __half2float(hi));
            }
            g_bhi[idx] = hi;
            g_blo[idx] = lo;
        } else {
            int j = idx - NHID*KPAD;
            if (j < NOUT*NHID) {
                float wv = wo[j];
                __half hi = __float2half_rn(wv);
                g_ohi[j] = hi;
                g_olo[j] = __float2half_rn(wv - __half2float(hi));
            }
        }
    }
}

// ================= GEMM1 (frozen R6 core; grid transposed: x=n-chunk, y=m-tile) =================
#define STAGE_BYTES 49152

__global__ void __launch_bounds__(256, 2) k_gemm1tc() {
    extern __shared__ char smem[];
    const int tid    = threadIdx.x;
    const int wid    = tid >> 5;
    const int lane   = tid & 31;
    const int warp_m = wid >> 1;
    const int warp_n = wid &  1;
    const int m_base = blockIdx.y * 128;     // transposed: co-resident CTAs share A tiles
    const int n_base = blockIdx.x * 128;

    const uint32_t sbase = smem_u32(smem);

    auto load_tile = [&](int kc, int s) {
        const uint32_t st = sbase + s * STAGE_BYTES;
        const int kcol = kc * 64;
        #pragma unroll
        for (int it = 0; it < 4; it++) {
            int g = it * 256 + tid;
            int row = g >> 3, sub = g & 7;
            uint32_t off = row * 128 + sub * 16;
            const char* src = (const char*)(g_a16 + (size_t)(m_base + row)*KPAD + kcol) + sub*16;
            CP_ASYNC16(st + SWZ(off), src);
        }
        #pragma unroll
        for (int it = 0; it < 4; it++) {
            int g = it * 256 + tid;
            int row = g >> 3, sub = g & 7;
            uint32_t off = row * 128 + sub * 16;
            const char* srch = (const char*)(g_bhi + (size_t)(n_base + row)*KPAD + kcol) + sub*16;
            const char* srcl = (const char*)(g_blo + (size_t)(n_base + row)*KPAD + kcol) + sub*16;
            CP_ASYNC16(st + 16384 + SWZ(off), srch);
            CP_ASYNC16(st + 32768 + SWZ(off), srcl);
        }
        CP_COMMIT();
    };

    float acc[2][8][4];
    #pragma unroll
    for (int i = 0; i < 2; i++)
        #pragma unroll
        for (int j = 0; j < 8; j++)
            #pragma unroll
            for (int q = 0; q < 4; q++) acc[i][j][q] = 0.f;

    load_tile(0, 0);

    const int lrow = lane & 15, lcol = (lane >> 4) * 16;

    #pragma unroll 1
    for (int c = 0; c < NCH; c++) {
        const int buf = c & 1;
        if (c + 1 < NCH) { load_tile(c + 1, buf ^ 1); CP_WAIT(1); }
        else            { CP_WAIT(0); }
        __syncthreads();

        const uint32_t sA = sbase + buf * STAGE_BYTES;
        const uint32_t sBh = sA + 16384;
        const uint32_t sBl = sA + 32768;

        #pragma unroll
        for (int ks = 0; ks < 4; ks++) {
            uint32_t a[2][4], bh[4][4], bl[4][4];
            #pragma unroll
            for (int mt = 0; mt < 2; mt++) {
                uint32_t off = (uint32_t)(warp_m*32 + mt*16 + lrow)*128 + ks*32 + lcol;
                LDSM_X4(a[mt][0], a[mt][1], a[mt][2], a[mt][3], sA + SWZ(off));
            }
            #pragma unroll
            for (int nt = 0; nt < 4; nt++) {
                uint32_t off = (uint32_t)(warp_n*64 + nt*16 + lrow)*128 + ks*32 + lcol;
                uint32_t so = SWZ(off);
                LDSM_X4(bh[nt][0], bh[nt][1], bh[nt][2], bh[nt][3], sBh + so);
                LDSM_X4(bl[nt][0], bl[nt][1], bl[nt][2], bl[nt][3], sBl + so);
            }
            #pragma unroll
            for (int mt = 0; mt < 2; mt++)
                #pragma unroll
                for (int nt = 0; nt < 4; nt++) {
                    MMA16816(acc[mt][nt*2+0], a[mt][0],a[mt][1],a[mt][2],a[mt][3],
                             bh[nt][0], bh[nt][2]);
                    MMA16816(acc[mt][nt*2+1], a[mt][0],a[mt][1],a[mt][2],a[mt][3],
                             bh[nt][1], bh[nt][3]);
                    MMA16816(acc[mt][nt*2+0], a[mt][0],a[mt][1],a[mt][2],a[mt][3],
                             bl[nt][0], bl[nt][2]);
                    MMA16816(acc[mt][nt*2+1], a[mt][0],a[mt][1],a[mt][2],a[mt][3],
                             bl[nt][1], bl[nt][3]);
                }
        }
        __syncthreads();
    }

    const int erow = lane >> 2, ecol = (lane & 3) * 2;
    #pragma unroll
    for (int mt = 0; mt < 2; mt++) {
        #pragma unroll
        for (int nt = 0; nt < 8; nt++) {
            int col = n_base + warp_n*64 + nt*8 + ecol;
            int r0  = m_base + warp_m*32 + mt*16 + erow;
            float2 v0; v0.x = acc[mt][nt][0]; v0.y = acc[mt][nt][1];
            float2 v1; v1.x = acc[mt][nt][2]; v1.y = acc[mt][nt][3];
            *(float2*)(g_ch + (size_t)r0*NHID + col)       = v0;
            *(float2*)(g_ch + (size_t)(r0 + 8)*NHID + col) = v1;
        }
    }
}

// ================= GEMM2 (reverted to measured-best R12 core): depth-2, 64-col, K=512 =================
__global__ void __launch_bounds__(256, 2) k_gemm2tc() {
    extern __shared__ char smem[];
    const int tid    = threadIdx.x;
    const int wid    = tid >> 5;
    const int lane   = tid & 31;
    const int warp_m = wid >> 1;
    const int warp_n = wid &  1;
    const int m_base = blockIdx.x * 128;

    const uint32_t sbase = smem_u32(smem);

    auto load_tile = [&](int kc, int s) {
        const uint32_t st = sbase + s * STAGE_BYTES;
        const int kcol = kc * 64;
        #pragma unroll
        for (int it = 0; it < 4; it++) {
            int g = it * 256 + tid;
            int row = g >> 3, sub = g & 7;
            uint32_t off = row * 128 + sub * 16;
            const char* src = (const char*)(g_sh + (size_t)(m_base + row)*NHID + kcol) + sub*16;
            CP_ASYNC16(st + SWZ(off), src);
        }
        #pragma unroll
        for (int it = 0; it < 4; it++) {
            int g = it * 256 + tid;
            int row = g >> 3, sub = g & 7;
            uint32_t off = row * 128 + sub * 16;
            const char* srch = (const char*)(g_ohi + (size_t)row*NHID + kcol) + sub*16;
            const char* srcl = (const char*)(g_olo + (size_t)row*NHID + kcol) + sub*16;
            CP_ASYNC16(st + 16384 + SWZ(off), srch);
            CP_ASYNC16(st + 32768 + SWZ(off), srcl);
        }
        CP_COMMIT();
    };

    float acc[2][8][4];
    #pragma unroll
    for (int i = 0; i < 2; i++)
        #pragma unroll
        for (int j = 0; j < 8; j++)
            #pragma unroll
            for (int q = 0; q < 4; q++) acc[i][j][q] = 0.f;

    load_tile(0, 0);

    const int lrow = lane & 15, lcol = (lane >> 4) * 16;

    #pragma unroll 1
    for (int c = 0; c < NCH2; c++) {
        const int buf = c & 1;
        if (c + 1 < NCH2) { load_tile(c + 1, buf ^ 1); CP_WAIT(1); }
        else             { CP_WAIT(0); }
        __syncthreads();

        const uint32_t sA = sbase + buf * STAGE_BYTES;
        const uint32_t sBh = sA + 16384;
        const uint32_t sBl = sA + 32768;

        #pragma unroll
        for (int ks = 0; ks < 4; ks++) {
            uint32_t a[2][4], bh[4][4], bl[4][4];
            #pragma unroll
            for (int mt = 0; mt < 2; mt++) {
                uint32_t off = (uint32_t)(warp_m*32 + mt*16 + lrow)*128 + ks*32 + lcol;
                LDSM_X4(a[mt][0], a[mt][1], a[mt][2], a[mt][3], sA + SWZ(off));
            }
            #pragma unroll
            for (int nt = 0; nt < 4; nt++) {
                uint32_t off = (uint32_t)(warp_n*64 + nt*16 + lrow)*128 + ks*32 + lcol;
                uint32_t so = SWZ(off);
                LDSM_X4(bh[nt][0], bh[nt][1], bh[nt][2], bh[nt][3], sBh + so);
                LDSM_X4(bl[nt][0], bl[nt][1], bl[nt][2], bl[nt][3], sBl + so);
            }
            #pragma unroll
            for (int mt = 0; mt < 2; mt++)
                #pragma unroll
                for (int nt = 0; nt < 4; nt++) {
                    MMA16816(acc[mt][nt*2+0], a[mt][0],a[mt][1],a[mt][2],a[mt][3],
                             bh[nt][0], bh[nt][2]);
                    MMA16816(acc[mt][nt*2+1], a[mt][0],a[mt][1],a[mt][2],a[mt][3],
                             bh[nt][1], bh[nt][3]);
                    MMA16816(acc[mt][nt*2+0], a[mt][0],a[mt][1],a[mt][2],a[mt][3],
                             bl[nt][0], bl[nt][2]);
                    MMA16816(acc[mt][nt*2+1], a[mt][0],a[mt][1],a[mt][2],a[mt][3],
                             bl[nt][1], bl[nt][3]);
                }
        }
        __syncthreads();
    }

    const int erow = lane >> 2, ecol = (lane & 3) * 2;
    #pragma unroll
    for (int mt = 0; mt < 2; mt++) {
        #pragma unroll
        for (int nt = 0; nt < 8; nt++) {
            int col = warp_n*64 + nt*8 + ecol;
            int r0  = m_base + warp_m*32 + mt*16 + erow;
            float2 v0; v0.x = acc[mt][nt][0]; v0.y = acc[mt][nt][1];
            float2 v1; v1.x = acc[mt][nt][2]; v1.y = acc[mt][nt][3];
            *(float2*)(g_co + (size_t)r0*NOUT + col)       = v0;
            *(float2*)(g_co + (size_t)(r0 + 8)*NOUT + col) = v1;
        }
    }
}

// ================= LIF scan: float2-wide, prefetch 16 =================
__global__ void k_lif() {
    int g2 = blockIdx.x*blockDim.x + threadIdx.x;   // pair index: 0 .. BB*NHID/2-1
    const float2* src = ((const float2*)g_ch) + g2;
    __half2*      dst = ((__half2*)g_sh) + g2;
    const int STRIDE2 = BB*NHID/2;                  // 32768 float2 per timestep
    float vx = 0.f, vy = 0.f, cx = 0.f, cy = 0.f;
    float2 xs[16];
    #pragma unroll
    for (int p = 0; p < 16; p++) xs[p] = __ldcs(src + (size_t)p*STRIDE2);
    #pragma unroll 1
    for (int t0 = 0; t0 < TT; t0 += 16) {
        #pragma unroll
        for (int p = 0; p < 16; p++) {
            float2 x = xs[p];
            int tn = t0 + 16 + p;
            if (tn < TT) xs[p] = __ldcs(src + (size_t)tn*STRIDE2);
            vx = vx + C_A*(cx - vx);
            vy = vy + C_A*(cy - vy);
            cx = cx*C_D + x.x;
            cy = cy*C_D + x.y;
            bool zx = vx > 1.0f, zy = vy > 1.0f;
            if (zx) vx = 0.f;
            if (zy) vy = 0.f;
            dst[(size_t)(t0 + p)*STRIDE2] = __floats2half2_rn(zx ? 1.f : 0.f,
                                                              zy ? 1.f : 0.f);
        }
    }
}

// ================= LI scan (prefetch 32) =================
__global__ void k_li(float* __restrict__ out) {
    int gid = blockIdx.x*blockDim.x + threadIdx.x;   // b*128 + o
    float v = 0.0f, cur = 0.0f;
    float xs[32];
    #pragma unroll
    for (int p = 0; p < 32; p++) xs[p] = __ldcs(g_co + p*(BB*NOUT) + gid);
    #pragma unroll 1
    for (int t0 = 0; t0 < TT; t0 += 32) {
        #pragma unroll
        for (int p = 0; p < 32; p++) {
            float x = xs[p];
            int tn = t0 + 32 + p;
            if (tn < TT) xs[p] = __ldcs(g_co + tn*(BB*NOUT) + gid);
            v   = v + C_A*(cur - v);
            cur = cur*C_D + x;
            __stcs(out + (t0 + p)*(BB*NOUT) + gid, v);
        }
    }
}

// ================= launch =================
extern "C" void kernel_launch(void* const* d_in, const int* in_sizes, int n_in,
                              void* d_out, int out_size) {
    const float *spikes = nullptr, *wh = nullptr, *wo = nullptr;
    for (int i = 0; i < n_in; i++) {
        if      (in_sizes[i] == TT*BB*NIN) spikes = (const float*)d_in[i];
        else if (in_sizes[i] == NHID*NIN)  wh     = (const float*)d_in[i];
        else if (in_sizes[i] == NOUT*NHID) wo     = (const float*)d_in[i];
    }
    cudaFuncSetAttribute(k_gemm1tc, cudaFuncAttributeMaxDynamicSharedMemorySize,
                         2*STAGE_BYTES);
    cudaFuncSetAttribute(k_gemm2tc, cudaFuncAttributeMaxDynamicSharedMemorySize,
                         2*STAGE_BYTES);
    k_prep   <<<A16_BLOCKS + WS_BLOCKS, 256>>>(spikes, wh, wo);
    k_gemm1tc<<<dim3(NHID/128, MTILES), 256, 2*STAGE_BYTES>>>();
    k_lif    <<<(BB*NHID/2)/128, 128>>>();
    k_gemm2tc<<<MTILES, 256, 2*STAGE_BYTES>>>();
    k_li     <<<(BB*NOUT)/64, 64>>>((float*)d_out);
}

// round 15
// speedup vs baseline: 1.0392x; 1.0161x over previous
#include <cuda_runtime.h>
#include <cuda_fp16.h>
#include <stdint.h>

// Problem constants
#define TT   256
#define BB   128
#define NIN  784
#define NHID 512
#define NOUT 128
#define MM   (TT*BB)        // 32768 (t,b) pairs
#define KPAD 832            // 784 padded to 13*64
#define NCH  13             // gemm1 K chunks of 64
#define NCH2 8              // gemm2 K chunks of 64 (512/64)
#define MTILES (MM/128)     // 256

// CUBA constants (exactly fp32-rounded like JAX)
#define C_A ((float)(1e-6*(1.0/6e-6)))           // 0.16666667f
#define C_D ((float)(1.0 - 1e-6*(1.0/6e-6)))     // 0.8333333f

// ---- scratch (device globals; no allocations allowed) ----
__device__ __half   g_a16 [(size_t)MM*KPAD];   // spikes fp16 K-padded    54.5 MB
__device__ __half   g_bhi [NHID*KPAD];         // w_hidden hi fp16        0.85 MB
__device__ __half   g_blo [NHID*KPAD];         // w_hidden lo fp16        0.85 MB
__device__ __half   g_ohi [NOUT*NHID];         // w_out hi fp16           128 KB
__device__ __half   g_olo [NOUT*NHID];         // w_out lo fp16           128 KB
__device__ float    g_ch  [(size_t)MM*NHID];   // hidden synaptic input   67 MB
__device__ __half   g_sh  [(size_t)MM*NHID];   // hidden spikes fp16      33.5 MB
__device__ float    g_co  [MM*NOUT];           // output synaptic input   16.8 MB

// ================= PTX helpers =================
__device__ __forceinline__ uint32_t smem_u32(const void* p) {
    uint32_t a;
    asm("{ .reg .u64 t; cvta.to.shared.u64 t, %1; cvt.u32.u64 %0, t; }" : "=r"(a) : "l"(p));
    return a;
}
#define CP_ASYNC16(dst, src) \
    asm volatile("cp.async.cg.shared.global [%0], [%1], 16;" :: "r"(dst), "l"(src))
#define CP_COMMIT()  asm volatile("cp.async.commit_group;" ::: "memory")
#define CP_WAIT(n)   asm volatile("cp.async.wait_group %0;" :: "n"(n) : "memory")

#define LDSM_X4(r0,r1,r2,r3, a) \
    asm volatile("ldmatrix.sync.aligned.m8n8.x4.shared.b16 {%0,%1,%2,%3}, [%4];" \
        : "=r"(r0),"=r"(r1),"=r"(r2),"=r"(r3) : "r"(a))
#define MMA16816(d, a0,a1,a2,a3, b0,b1) \
    asm volatile("mma.sync.aligned.m16n8k16.row.col.f32.f16.f16.f32 " \
        "{%0,%1,%2,%3}, {%4,%5,%6,%7}, {%8,%9}, {%0,%1,%2,%3};" \
        : "+f"((d)[0]),"+f"((d)[1]),"+f"((d)[2]),"+f"((d)[3]) \
        : "r"(a0),"r"(a1),"r"(a2),"r"(a3),"r"(b0),"r"(b1))

#define SWZ(off) ((off) ^ (((off) >> 3) & 0x70))

// PDL: wait for the prior kernel's writes before dependent reads
#define GRID_DEP_SYNC() cudaGridDependencySynchronize()

// ================= prep kernel: A conversion + weight splits, fused =================
#define AGRP 104
#define A16_BLOCKS ((MM*AGRP + 255)/256)
#define WS_ELEMS   (NHID*KPAD + NOUT*NHID)
#define WS_BLOCKS  ((WS_ELEMS + 255)/256)

__global__ void k_prep(const float* __restrict__ spikes,
                       const float* __restrict__ wh,
                       const float* __restrict__ wo) {
    if (blockIdx.x < A16_BLOCKS) {
        int idx = blockIdx.x*blockDim.x + threadIdx.x;
        if (idx >= MM*AGRP) return;
        int m = idx / AGRP, grp = idx - m*AGRP;
        uint4 out;
        if (grp < 98) {
            const float4* src = (const float4*)(spikes + (size_t)m*NIN + grp*8);
            float4 v0 = __ldcs(src);
            float4 v1 = __ldcs(src + 1);
            __half2 h0 = __floats2half2_rn(v0.x, v0.y);
            __half2 h1 = __floats2half2_rn(v0.z, v0.w);
            __half2 h2 = __floats2half2_rn(v1.x, v1.y);
            __half2 h3 = __floats2half2_rn(v1.z, v1.w);
            out.x = *(uint32_t*)&h0; out.y = *(uint32_t*)&h1;
            out.z = *(uint32_t*)&h2; out.w = *(uint32_t*)&h3;
        } else {
            out.x = out.y = out.z = out.w = 0u;
        }
        // plain store: g_a16 is re-read 4x by gemm1 -> keep L2-resident
        *(uint4*)(g_a16 + (size_t)m*KPAD + grp*8) = out;
    } else {
        int idx = (blockIdx.x - A16_BLOCKS)*blockDim.x + threadIdx.x;
        if (idx < NHID*KPAD) {
            int h = idx / KPAD, k = idx - h*KPAD;
            __half hi = __float2half_rn(0.f), lo = __float2half_rn(0.f);
            if (k < NIN) {
                float wv = wh[h*NIN + k];
                hi = __float2half_rn(wv);
                lo = __float2half_rn(wv - __half2float(hi));
            }
            g_bhi[idx] = hi;
            g_blo[idx] = lo;
        } else {
            int j = idx - NHID*KPAD;
            if (j < NOUT*NHID) {
                float wv = wo[j];
                __half hi = __float2half_rn(wv);
                g_ohi[j] = hi;
                g_olo[j] = __float2half_rn(wv - __half2float(hi));
            }
        }
    }
}

// ================= GEMM1 (frozen R6 core; grid transposed: x=n-chunk, y=m-tile) =================
#define STAGE_BYTES 49152

__global__ void __launch_bounds__(256, 2) k_gemm1tc() {
    extern __shared__ char smem[];
    const int tid    = threadIdx.x;
    const int wid    = tid >> 5;
    const int lane   = tid & 31;
    const int warp_m = wid >> 1;
    const int warp_n = wid &  1;
    const int m_base = blockIdx.y * 128;     // transposed: co-resident CTAs share A tiles
    const int n_base = blockIdx.x * 128;

    const uint32_t sbase = smem_u32(smem);

    auto load_tile = [&](int kc, int s) {
        const uint32_t st = sbase + s * STAGE_BYTES;
        const int kcol = kc * 64;
        #pragma unroll
        for (int it = 0; it < 4; it++) {
            int g = it * 256 + tid;
            int row = g >> 3, sub = g & 7;
            uint32_t off = row * 128 + sub * 16;
            const char* src = (const char*)(g_a16 + (size_t)(m_base + row)*KPAD + kcol) + sub*16;
            CP_ASYNC16(st + SWZ(off), src);
        }
        #pragma unroll
        for (int it = 0; it < 4; it++) {
            int g = it * 256 + tid;
            int row = g >> 3, sub = g & 7;
            uint32_t off = row * 128 + sub * 16;
            const char* srch = (const char*)(g_bhi + (size_t)(n_base + row)*KPAD + kcol) + sub*16;
            const char* srcl = (const char*)(g_blo + (size_t)(n_base + row)*KPAD + kcol) + sub*16;
            CP_ASYNC16(st + 16384 + SWZ(off), srch);
            CP_ASYNC16(st + 32768 + SWZ(off), srcl);
        }
        CP_COMMIT();
    };

    float acc[2][8][4];
    #pragma unroll
    for (int i = 0; i < 2; i++)
        #pragma unroll
        for (int j = 0; j < 8; j++)
            #pragma unroll
            for (int q = 0; q < 4; q++) acc[i][j][q] = 0.f;

    GRID_DEP_SYNC();                 // wait for k_prep output before first load
    load_tile(0, 0);

    const int lrow = lane & 15, lcol = (lane >> 4) * 16;

    #pragma unroll 1
    for (int c = 0; c < NCH; c++) {
        const int buf = c & 1;
        if (c + 1 < NCH) { load_tile(c + 1, buf ^ 1); CP_WAIT(1); }
        else            { CP_WAIT(0); }
        __syncthreads();

        const uint32_t sA = sbase + buf * STAGE_BYTES;
        const uint32_t sBh = sA + 16384;
        const uint32_t sBl = sA + 32768;

        #pragma unroll
        for (int ks = 0; ks < 4; ks++) {
            uint32_t a[2][4], bh[4][4], bl[4][4];
            #pragma unroll
            for (int mt = 0; mt < 2; mt++) {
                uint32_t off = (uint32_t)(warp_m*32 + mt*16 + lrow)*128 + ks*32 + lcol;
                LDSM_X4(a[mt][0], a[mt][1], a[mt][2], a[mt][3], sA + SWZ(off));
            }
            #pragma unroll
            for (int nt = 0; nt < 4; nt++) {
                uint32_t off = (uint32_t)(warp_n*64 + nt*16 + lrow)*128 + ks*32 + lcol;
                uint32_t so = SWZ(off);
                LDSM_X4(bh[nt][0], bh[nt][1], bh[nt][2], bh[nt][3], sBh + so);
                LDSM_X4(bl[nt][0], bl[nt][1], bl[nt][2], bl[nt][3], sBl + so);
            }
            #pragma unroll
            for (int mt = 0; mt < 2; mt++)
                #pragma unroll
                for (int nt = 0; nt < 4; nt++) {
                    MMA16816(acc[mt][nt*2+0], a[mt][0],a[mt][1],a[mt][2],a[mt][3],
                             bh[nt][0], bh[nt][2]);
                    MMA16816(acc[mt][nt*2+1], a[mt][0],a[mt][1],a[mt][2],a[mt][3],
                             bh[nt][1], bh[nt][3]);
                    MMA16816(acc[mt][nt*2+0], a[mt][0],a[mt][1],a[mt][2],a[mt][3],
                             bl[nt][0], bl[nt][2]);
                    MMA16816(acc[mt][nt*2+1], a[mt][0],a[mt][1],a[mt][2],a[mt][3],
                             bl[nt][1], bl[nt][3]);
                }
        }
        __syncthreads();
    }

    const int erow = lane >> 2, ecol = (lane & 3) * 2;
    #pragma unroll
    for (int mt = 0; mt < 2; mt++) {
        #pragma unroll
        for (int nt = 0; nt < 8; nt++) {
            int col = n_base + warp_n*64 + nt*8 + ecol;
            int r0  = m_base + warp_m*32 + mt*16 + erow;
            float2 v0; v0.x = acc[mt][nt][0]; v0.y = acc[mt][nt][1];
            float2 v1; v1.x = acc[mt][nt][2]; v1.y = acc[mt][nt][3];
            *(float2*)(g_ch + (size_t)r0*NHID + col)       = v0;
            *(float2*)(g_ch + (size_t)(r0 + 8)*NHID + col) = v1;
        }
    }
}

// ================= GEMM2 (R12 core): depth-2, 64-col, K=512 =================
__global__ void __launch_bounds__(256, 2) k_gemm2tc() {
    extern __shared__ char smem[];
    const int tid    = threadIdx.x;
    const int wid    = tid >> 5;
    const int lane   = tid & 31;
    const int warp_m = wid >> 1;
    const int warp_n = wid &  1;
    const int m_base = blockIdx.x * 128;

    const uint32_t sbase = smem_u32(smem);

    auto load_tile = [&](int kc, int s) {
        const uint32_t st = sbase + s * STAGE_BYTES;
        const int kcol = kc * 64;
        #pragma unroll
        for (int it = 0; it < 4; it++) {
            int g = it * 256 + tid;
            int row = g >> 3, sub = g & 7;
            uint32_t off = row * 128 + sub * 16;
            const char* src = (const char*)(g_sh + (size_t)(m_base + row)*NHID + kcol) + sub*16;
            CP_ASYNC16(st + SWZ(off), src);
        }
        #pragma unroll
        for (int it = 0; it < 4; it++) {
            int g = it * 256 + tid;
            int row = g >> 3, sub = g & 7;
            uint32_t off = row * 128 + sub * 16;
            const char* srch = (const char*)(g_ohi + (size_t)row*NHID + kcol) + sub*16;
            const char* srcl = (const char*)(g_olo + (size_t)row*NHID + kcol) + sub*16;
            CP_ASYNC16(st + 16384 + SWZ(off), srch);
            CP_ASYNC16(st + 32768 + SWZ(off), srcl);
        }
        CP_COMMIT();
    };

    float acc[2][8][4];
    #pragma unroll
    for (int i = 0; i < 2; i++)
        #pragma unroll
        for (int j = 0; j < 8; j++)
            #pragma unroll
            for (int q = 0; q < 4; q++) acc[i][j][q] = 0.f;

    GRID_DEP_SYNC();                 // wait for k_lif output
    load_tile(0, 0);

    const int lrow = lane & 15, lcol = (lane >> 4) * 16;

    #pragma unroll 1
    for (int c = 0; c < NCH2; c++) {
        const int buf = c & 1;
        if (c + 1 < NCH2) { load_tile(c + 1, buf ^ 1); CP_WAIT(1); }
        else             { CP_WAIT(0); }
        __syncthreads();

        const uint32_t sA = sbase + buf * STAGE_BYTES;
        const uint32_t sBh = sA + 16384;
        const uint32_t sBl = sA + 32768;

        #pragma unroll
        for (int ks = 0; ks < 4; ks++) {
            uint32_t a[2][4], bh[4][4], bl[4][4];
            #pragma unroll
            for (int mt = 0; mt < 2; mt++) {
                uint32_t off = (uint32_t)(warp_m*32 + mt*16 + lrow)*128 + ks*32 + lcol;
                LDSM_X4(a[mt][0], a[mt][1], a[mt][2], a[mt][3], sA + SWZ(off));
            }
            #pragma unroll
            for (int nt = 0; nt < 4; nt++) {
                uint32_t off = (uint32_t)(warp_n*64 + nt*16 + lrow)*128 + ks*32 + lcol;
                uint32_t so = SWZ(off);
                LDSM_X4(bh[nt][0], bh[nt][1], bh[nt][2], bh[nt][3], sBh + so);
                LDSM_X4(bl[nt][0], bl[nt][1], bl[nt][2], bl[nt][3], sBl + so);
            }
            #pragma unroll
            for (int mt = 0; mt < 2; mt++)
                #pragma unroll
                for (int nt = 0; nt < 4; nt++) {
                    MMA16816(acc[mt][nt*2+0], a[mt][0],a[mt][1],a[mt][2],a[mt][3],
                             bh[nt][0], bh[nt][2]);
                    MMA16816(acc[mt][nt*2+1], a[mt][0],a[mt][1],a[mt][2],a[mt][3],
                             bh[nt][1], bh[nt][3]);
                    MMA16816(acc[mt][nt*2+0], a[mt][0],a[mt][1],a[mt][2],a[mt][3],
                             bl[nt][0], bl[nt][2]);
                    MMA16816(acc[mt][nt*2+1], a[mt][0],a[mt][1],a[mt][2],a[mt][3],
                             bl[nt][1], bl[nt][3]);
                }
        }
        __syncthreads();
    }

    const int erow = lane >> 2, ecol = (lane & 3) * 2;
    #pragma unroll
    for (int mt = 0; mt < 2; mt++) {
        #pragma unroll
        for (int nt = 0; nt < 8; nt++) {
            int col = warp_n*64 + nt*8 + ecol;
            int r0  = m_base + warp_m*32 + mt*16 + erow;
            float2 v0; v0.x = acc[mt][nt][0]; v0.y = acc[mt][nt][1];
            float2 v1; v1.x = acc[mt][nt][2]; v1.y = acc[mt][nt][3];
            *(float2*)(g_co + (size_t)r0*NOUT + col)       = v0;
            *(float2*)(g_co + (size_t)(r0 + 8)*NOUT + col) = v1;
        }
    }
}

// ================= LIF scan: float2-wide, prefetch 16 =================
__global__ void k_lif() {
    int g2 = blockIdx.x*blockDim.x + threadIdx.x;   // pair index: 0 .. BB*NHID/2-1
    const float2* src = ((const float2*)g_ch) + g2;
    __half2*      dst = ((__half2*)g_sh) + g2;
    const int STRIDE2 = BB*NHID/2;                  // 32768 float2 per timestep
    float vx = 0.f, vy = 0.f, cx = 0.f, cy = 0.f;
    float2 xs[16];
    GRID_DEP_SYNC();                 // wait for k_gemm1tc output
    #pragma unroll
    for (int p = 0; p < 16; p++) xs[p] = __ldcs(src + (size_t)p*STRIDE2);
    #pragma unroll 1
    for (int t0 = 0; t0 < TT; t0 += 16) {
        #pragma unroll
        for (int p = 0; p < 16; p++) {
            float2 x = xs[p];
            int tn = t0 + 16 + p;
            if (tn < TT) xs[p] = __ldcs(src + (size_t)tn*STRIDE2);
            vx = vx + C_A*(cx - vx);
            vy = vy + C_A*(cy - vy);
            cx = cx*C_D + x.x;
            cy = cy*C_D + x.y;
            bool zx = vx > 1.0f, zy = vy > 1.0f;
            if (zx) vx = 0.f;
            if (zy) vy = 0.f;
            dst[(size_t)(t0 + p)*STRIDE2] = __floats2half2_rn(zx ? 1.f : 0.f,
                                                              zy ? 1.f : 0.f);
        }
    }
}

// ================= LI scan (prefetch 32) =================
__global__ void k_li(float* __restrict__ out) {
    int gid = blockIdx.x*blockDim.x + threadIdx.x;   // b*128 + o
    float v = 0.0f, cur = 0.0f;
    float xs[32];
    GRID_DEP_SYNC();                 // wait for k_gemm2tc output
    #pragma unroll
    for (int p = 0; p < 32; p++) xs[p] = __ldcs(g_co + p*(BB*NOUT) + gid);
    #pragma unroll 1
    for (int t0 = 0; t0 < TT; t0 += 32) {
        #pragma unroll
        for (int p = 0; p < 32; p++) {
            float x = xs[p];
            int tn = t0 + 32 + p;
            if (tn < TT) xs[p] = __ldcs(g_co + tn*(BB*NOUT) + gid);
            v   = v + C_A*(cur - v);
            cur = cur*C_D + x;
            __stcs(out + (t0 + p)*(BB*NOUT) + gid, v);
        }
    }
}

// ================= launch =================
template <typename F, typename... Args>
static void launch_pdl(F f, dim3 grid, dim3 block, size_t smem, Args... args) {
    cudaLaunchAttribute attr[1];
    attr[0].id = cudaLaunchAttributeProgrammaticStreamSerialization;
    attr[0].val.programmaticStreamSerializationAllowed = 1;
    cudaLaunchConfig_t cfg = {};
    cfg.gridDim = grid;
    cfg.blockDim = block;
    cfg.dynamicSmemBytes = smem;
    cfg.stream = 0;
    cfg.attrs = attr;
    cfg.numAttrs = 1;
    cudaLaunchKernelEx(&cfg, f, args...);
}

extern "C" void kernel_launch(void* const* d_in, const int* in_sizes, int n_in,
                              void* d_out, int out_size) {
    const float *spikes = nullptr, *wh = nullptr, *wo = nullptr;
    for (int i = 0; i < n_in; i++) {
        if      (in_sizes[i] == TT*BB*NIN) spikes = (const float*)d_in[i];
        else if (in_sizes[i] == NHID*NIN)  wh     = (const float*)d_in[i];
        else if (in_sizes[i] == NOUT*NHID) wo     = (const float*)d_in[i];
    }
    cudaFuncSetAttribute(k_gemm1tc, cudaFuncAttributeMaxDynamicSharedMemorySize,
                         2*STAGE_BYTES);
    cudaFuncSetAttribute(k_gemm2tc, cudaFuncAttributeMaxDynamicSharedMemorySize,
                         2*STAGE_BYTES);
    k_prep<<<A16_BLOCKS + WS_BLOCKS, 256>>>(spikes, wh, wo);
    launch_pdl(k_gemm1tc, dim3(NHID/128, MTILES), dim3(256), 2*STAGE_BYTES);
    launch_pdl(k_lif,     dim3((BB*NHID/2)/128),  dim3(128), 0);
    launch_pdl(k_gemm2tc, dim3(MTILES),           dim3(256), 2*STAGE_BYTES);
    launch_pdl(k_li,      dim3((BB*NOUT)/64),     dim3(64),  0, (float*)d_out);
}